// round 2
// baseline (speedup 1.0000x reference)
#include <cuda_runtime.h>
#include <math.h>

// Fused LayerNorm(768) -> Linear(768->64) -> SiLU -> unpatchify
// fp32 FFMA baseline. W' (lnw-folded, transposed, swizzled) lives in smem.

#define THREADS 512
#define WARPS 16
#define RPW 4                    // rows per warp
#define ROWS_PER_TILE (WARPS*RPW) // 64
#define KDIM 768
#define ODIM 64
#define NROWS (2048*64)
#define NTILES (NROWS/ROWS_PER_TILE) // 2048

// smem floats: Ws 768*64 = 49152 | xns 16*4*128 = 8192 | bsp 64
#define WS_FLOATS (KDIM*ODIM)
#define XNS_FLOATS (WARPS*RPW*128)
#define SMEM_FLOATS (WS_FLOATS + XNS_FLOATS + 64)
#define SMEM_BYTES (SMEM_FLOATS*4)

// pair-swizzled W layout: row k holds 32 float2 pairs, pair index = (o>>1)^(k&31)
__device__ __forceinline__ int ws_off(int k, int pair) {
    return k*64 + (((pair) ^ (k & 31)) << 1);
}

extern __shared__ float smem[];

__global__ void __launch_bounds__(THREADS, 1)
fused_ln_linear_silu(const float* __restrict__ x,
                     const float* __restrict__ lnw,
                     const float* __restrict__ lnb,
                     const float* __restrict__ W,
                     const float* __restrict__ b,
                     float* __restrict__ out)
{
    float* Ws  = smem;
    float* xns = smem + WS_FLOATS;
    float* bsp = smem + WS_FLOATS + XNS_FLOATS;

    const int tid  = threadIdx.x;
    const int lane = tid & 31;
    const int warp = tid >> 5;

    // ---- one-time per block: fill swizzled W' = W * lnw (transposed) ----
    // thread owns k; loop over o. LDG: lanes have consecutive k, same o -> coalesced.
    // STS: banks = perm(lane) via XOR swizzle -> conflict-free.
    for (int k = tid; k < KDIM; k += THREADS) {
        float lw = lnw[k];
        #pragma unroll 4
        for (int o = 0; o < ODIM; o++) {
            Ws[ws_off(k, o >> 1) + (o & 1)] = W[o*KDIM + k] * lw;
        }
    }
    // b'[o] = b[o] + sum_k lnb[k]*W[o,k]
    if (tid < ODIM) {
        float s = 0.f;
        const float* wr = W + tid*KDIM;
        for (int k = 0; k < KDIM; k++) s += lnb[k] * wr[k];
        bsp[tid] = b[tid] + s;
    }
    __syncthreads();

    float* xw = xns + warp * (RPW*128);

    for (int tile = blockIdx.x; tile < NTILES; tile += gridDim.x) {
        const int rbase = tile*ROWS_PER_TILE + warp*RPW;

        // ---- LayerNorm: z = (x - mu) * rstd, fully in registers ----
        float4 xr[RPW][6];
        #pragma unroll
        for (int r = 0; r < RPW; r++) {
            const float4* xp = (const float4*)(x + (size_t)(rbase + r) * KDIM);
            float s = 0.f, ss = 0.f;
            #pragma unroll
            for (int i = 0; i < 6; i++) {
                float4 v = xp[i*32 + lane];    // k = i*128 + lane*4 + c
                xr[r][i] = v;
                s  += v.x + v.y + v.z + v.w;
                ss += v.x*v.x + v.y*v.y + v.z*v.z + v.w*v.w;
            }
            #pragma unroll
            for (int d = 16; d; d >>= 1) {
                s  += __shfl_xor_sync(0xffffffffu, s,  d);
                ss += __shfl_xor_sync(0xffffffffu, ss, d);
            }
            const float mu   = s * (1.f/768.f);
            const float var  = ss * (1.f/768.f) - mu*mu;
            const float rstd = rsqrtf(var + 1e-5f);
            #pragma unroll
            for (int i = 0; i < 6; i++) {
                xr[r][i].x = (xr[r][i].x - mu) * rstd;
                xr[r][i].y = (xr[r][i].y - mu) * rstd;
                xr[r][i].z = (xr[r][i].z - mu) * rstd;
                xr[r][i].w = (xr[r][i].w - mu) * rstd;
            }
        }

        // ---- GEMM: each lane accumulates outputs o=2*lane, 2*lane+1 for 4 rows ----
        float acc[RPW][2];
        #pragma unroll
        for (int r = 0; r < RPW; r++) { acc[r][0] = 0.f; acc[r][1] = 0.f; }

        #pragma unroll
        for (int i = 0; i < 6; i++) {           // 128-k chunks
            __syncwarp();
            #pragma unroll
            for (int r = 0; r < RPW; r++)
                *(float4*)&xw[r*128 + lane*4] = xr[r][i];
            __syncwarp();

            #pragma unroll 4
            for (int s = 0; s < 32; s++) {
                const int k0 = i*128 + s*4;
                const float2 w0 = *(const float2*)&Ws[ws_off(k0 + 0, lane)];
                const float2 w1 = *(const float2*)&Ws[ws_off(k0 + 1, lane)];
                const float2 w2 = *(const float2*)&Ws[ws_off(k0 + 2, lane)];
                const float2 w3 = *(const float2*)&Ws[ws_off(k0 + 3, lane)];
                #pragma unroll
                for (int r = 0; r < RPW; r++) {
                    const float4 v = *(const float4*)&xw[r*128 + s*4]; // broadcast
                    acc[r][0] += v.x * w0.x;  acc[r][1] += v.x * w0.y;
                    acc[r][0] += v.y * w1.x;  acc[r][1] += v.y * w1.y;
                    acc[r][0] += v.z * w2.x;  acc[r][1] += v.z * w2.y;
                    acc[r][0] += v.w * w3.x;  acc[r][1] += v.w * w3.y;
                }
            }
        }

        // ---- epilogue: bias + SiLU + unpatchify scatter ----
        #pragma unroll
        for (int r = 0; r < RPW; r++) {
            const int row = rbase + r;
            const int bidx = row >> 6;
            const int c64  = row & 63;
            #pragma unroll
            for (int j = 0; j < 2; j++) {
                const int o = 2*lane + j;
                float y = acc[r][j] + bsp[o];
                float sv = y / (1.f + __expf(-y));
                const int ch = o >> 4;
                const int rr = ((c64 >> 3) << 2) + ((o >> 2) & 3);
                const int cl = ((c64 & 7) << 2) + (o & 3);
                out[(((size_t)bidx*4 + ch)*32 + rr)*32 + cl] = sv;
            }
        }
    }
}

extern "C" void kernel_launch(void* const* d_in, const int* in_sizes, int n_in,
                              void* d_out, int out_size)
{
    const float* x   = (const float*)d_in[0];
    const float* lnw = (const float*)d_in[1];
    const float* lnb = (const float*)d_in[2];
    const float* W   = (const float*)d_in[3];
    const float* b   = (const float*)d_in[4];
    float* out = (float*)d_out;

    cudaFuncSetAttribute(fused_ln_linear_silu,
                         cudaFuncAttributeMaxDynamicSharedMemorySize, SMEM_BYTES);

    int dev = 0, sms = 148;
    cudaGetDevice(&dev);
    cudaDeviceGetAttribute(&sms, cudaDevAttrMultiProcessorCount, dev);
    int grid = sms < NTILES ? sms : NTILES;

    fused_ln_linear_silu<<<grid, THREADS, SMEM_BYTES>>>(x, lnw, lnb, W, b, out);
}

// round 5
// speedup vs baseline: 1.4066x; 1.4066x over previous
#include <cuda_runtime.h>
#include <cstdint>
#include <math.h>

// LayerNorm(768) -> Linear(768->64) -> SiLU -> unpatchify, fused.
// LN folded into epilogue: y = rstd*(x@W'^T - mu*S) + b', W' = W*ln_w.
// tf32 mma.sync.m16n8k8 (plain sm_103 legal). W' resident in smem;
// x streamed through double-buffered 128x32 swizzled slabs.

#define THREADS 256
#define WARPS 8
#define KDIM 768
#define ODIM 64
#define TILE_M 128
#define NTILES 1024            // 131072 / 128
#define NSLABS 24              // K slabs of 32

// smem float offsets
#define WF_OFF 0               // 24 chunks * 64 o * 8 k = 49152 floats
#define XB_OFF 49152           // 2 buffers * 128*32 = 8192 floats
#define MU_OFF (XB_OFF + 8192) // 128
#define RS_OFF (MU_OFF + 128)  // 128
#define S_OFF  (RS_OFF + 128)  // 64
#define BP_OFF (S_OFF + 64)    // 64
#define SMEM_FLOATS (BP_OFF + 64)
#define SMEM_BYTES (SMEM_FLOATS * 4)   // 230912 B <= 232448

static __device__ __forceinline__ uint32_t f2tf(float f) {
    uint32_t r; asm("cvt.rna.tf32.f32 %0, %1;" : "=r"(r) : "f"(f)); return r;
}

static __device__ __forceinline__ void mma_tf32(float* d, const uint32_t* a, const uint32_t* b) {
    asm volatile(
        "mma.sync.aligned.m16n8k8.row.col.f32.tf32.tf32.f32 "
        "{%0,%1,%2,%3}, {%4,%5,%6,%7}, {%8,%9}, {%0,%1,%2,%3};"
        : "+f"(d[0]), "+f"(d[1]), "+f"(d[2]), "+f"(d[3])
        : "r"(a[0]), "r"(a[1]), "r"(a[2]), "r"(a[3]), "r"(b[0]), "r"(b[1]));
}

extern __shared__ float smem[];

__global__ void __launch_bounds__(THREADS, 1)
ln_gemm_silu(const float* __restrict__ x,
             const float* __restrict__ lnw,
             const float* __restrict__ lnb,
             const float* __restrict__ W,
             const float* __restrict__ b,
             float* __restrict__ out)
{
    const int tid  = threadIdx.x;
    const int lane = tid & 31;
    const int warp = tid >> 5;

    // ---------- one-time: W' = tf32(W * lnw), chunked + pair-interleaved ----------
    // chunk c holds k = 8c..8c+7; element (o,k) at c*512 + o*8 + (k&3)*2 + (k>>2)
    // -> a B fragment (b0=k, b1=k+4) is one aligned float2.
    for (int idx = tid; idx < ODIM * KDIM; idx += THREADS) {
        int o = idx / KDIM, k = idx - o * KDIM;
        uint32_t t = f2tf(W[idx] * lnw[k]);
        int c = k >> 3, kl = k & 7;
        smem[WF_OFF + c * 512 + o * 8 + (kl & 3) * 2 + (kl >> 2)] = __uint_as_float(t);
    }
    // S[o] = sum_k tf32(W'), b'[o] = b[o] + sum_k lnb*W
    if (tid < ODIM) {
        const float* wr = W + tid * KDIM;
        float s = 0.f, bs = 0.f;
        #pragma unroll 4
        for (int k = 0; k < KDIM; k++) {
            s  += __uint_as_float(f2tf(wr[k] * lnw[k]));
            bs += lnb[k] * wr[k];
        }
        smem[S_OFF  + tid] = s;
        smem[BP_OFF + tid] = b[tid] + bs;
    }
    __syncthreads();

    // roles: 8 warps = 4 row-groups x 2 o-halves
    const int rg = warp >> 1;          // rows rg*32 .. rg*32+31
    const int oh = warp & 1;           // outputs oh*32 .. oh*32+31

    // producer mapping: warp w fills rows w*16..w*16+15; lane -> (row, g)
    const int prow = warp * 16 + (lane >> 3);   // + i*4, i=0..3
    const int pg   = lane & 7;                  // float4 index within 32-k slab

    // precomputed swizzled STS float offsets (relative to buffer base)
    int sts_off[4];
    #pragma unroll
    for (int i = 0; i < 4; i++) {
        int r = prow + i * 4;
        sts_off[i] = r * 32 + ((pg ^ (r & 7)) << 2);
    }

    // consumer A-fragment row bases
    const int q = lane & 3;
    const int r0m[2] = { rg * 32 + (lane >> 2), rg * 32 + 16 + (lane >> 2) };

    for (int tile = blockIdx.x; tile < NTILES; tile += gridDim.x) {
        float acc[2][4][4];
        #pragma unroll
        for (int mt = 0; mt < 2; mt++)
            #pragma unroll
            for (int nt = 0; nt < 4; nt++)
                #pragma unroll
                for (int c = 0; c < 4; c++) acc[mt][nt][c] = 0.f;

        float st_s[4]  = {0.f, 0.f, 0.f, 0.f};
        float st_ss[4] = {0.f, 0.f, 0.f, 0.f};

        const float4* xt = (const float4*)x + (size_t)tile * TILE_M * 192;

        // ---- prologue: slab 0 ----
        float4 pv[4];
        #pragma unroll
        for (int i = 0; i < 4; i++)
            pv[i] = xt[(size_t)(prow + i * 4) * 192 + pg];
        #pragma unroll
        for (int i = 0; i < 4; i++) {
            float4 v = pv[i];
            st_s[i]  += v.x + v.y + v.z + v.w;
            st_ss[i] += v.x*v.x + v.y*v.y + v.z*v.z + v.w*v.w;
            float4 t;
            t.x = __uint_as_float(f2tf(v.x)); t.y = __uint_as_float(f2tf(v.y));
            t.z = __uint_as_float(f2tf(v.z)); t.w = __uint_as_float(f2tf(v.w));
            *(float4*)&smem[XB_OFF + sts_off[i]] = t;
        }
        __syncthreads();

        for (int s = 0; s < NSLABS; s++) {
            const int cur = s & 1;
            // prefetch next slab
            if (s + 1 < NSLABS) {
                #pragma unroll
                for (int i = 0; i < 4; i++)
                    pv[i] = xt[(size_t)(prow + i * 4) * 192 + (s + 1) * 8 + pg];
            }

            // ---- compute 4 k-chunks of this slab ----
            const float* xb = smem + XB_OFF + cur * 4096;
            #pragma unroll
            for (int cl = 0; cl < 4; cl++) {
                const int chunk = s * 4 + cl;
                uint32_t bf[4][2];
                #pragma unroll
                for (int nt = 0; nt < 4; nt++) {
                    const float* bp2 = smem + WF_OFF + chunk * 512
                                     + (oh * 32 + nt * 8 + (lane >> 2)) * 8 + q * 2;
                    uint2 bv = *(const uint2*)bp2;
                    bf[nt][0] = bv.x; bf[nt][1] = bv.y;
                }
                #pragma unroll
                for (int mt = 0; mt < 2; mt++) {
                    const int r = r0m[mt];
                    const int sw0 = ((cl * 2)     ^ (r & 7)) << 2;  // same for r and r+8
                    const int sw1 = ((cl * 2 + 1) ^ (r & 7)) << 2;
                    uint32_t af[4];
                    af[0] = __float_as_uint(xb[r * 32 + sw0 + q]);
                    af[1] = __float_as_uint(xb[(r + 8) * 32 + sw0 + q]);
                    af[2] = __float_as_uint(xb[r * 32 + sw1 + q]);
                    af[3] = __float_as_uint(xb[(r + 8) * 32 + sw1 + q]);
                    #pragma unroll
                    for (int nt = 0; nt < 4; nt++)
                        mma_tf32(acc[mt][nt], af, bf[nt]);
                }
            }

            // stats + STS for next slab
            if (s + 1 < NSLABS) {
                const int nxt = (s + 1) & 1;
                #pragma unroll
                for (int i = 0; i < 4; i++) {
                    float4 v = pv[i];
                    st_s[i]  += v.x + v.y + v.z + v.w;
                    st_ss[i] += v.x*v.x + v.y*v.y + v.z*v.z + v.w*v.w;
                    float4 t;
                    t.x = __uint_as_float(f2tf(v.x)); t.y = __uint_as_float(f2tf(v.y));
                    t.z = __uint_as_float(f2tf(v.z)); t.w = __uint_as_float(f2tf(v.w));
                    *(float4*)&smem[XB_OFF + nxt * 4096 + sts_off[i]] = t;
                }
            }
            __syncthreads();
        }

        // ---- row stats: reduce across the 8 lanes sharing each row ----
        #pragma unroll
        for (int i = 0; i < 4; i++) {
            #pragma unroll
            for (int d = 1; d < 8; d <<= 1) {
                st_s[i]  += __shfl_xor_sync(0xffffffffu, st_s[i],  d);
                st_ss[i] += __shfl_xor_sync(0xffffffffu, st_ss[i], d);
            }
        }
        if ((lane & 7) == 0) {
            #pragma unroll
            for (int i = 0; i < 4; i++) {
                int row = prow + i * 4;
                float mu = st_s[i] * (1.f / 768.f);
                float rs = rsqrtf(st_ss[i] * (1.f / 768.f) - mu * mu + 1e-5f);
                smem[MU_OFF + row] = mu;
                smem[RS_OFF + row] = rs;
            }
        }
        __syncthreads();

        // ---- epilogue: LN-correct, bias, SiLU, unpatchify ----
        #pragma unroll
        for (int mt = 0; mt < 2; mt++) {
            #pragma unroll
            for (int h = 0; h < 2; h++) {
                const int rowl = r0m[mt] + h * 8;
                const int grow = tile * TILE_M + rowl;
                const float mu   = smem[MU_OFF + rowl];
                const float rstd = smem[RS_OFF + rowl];
                const int bidx = grow >> 6;
                const int c64  = grow & 63;
                const int rrb  = (c64 >> 3) << 2;
                const int clb  = (c64 & 7) << 2;
                float* outb = out + ((size_t)bidx << 12);
                #pragma unroll
                for (int nt = 0; nt < 4; nt++) {
                    #pragma unroll
                    for (int c = 0; c < 2; c++) {
                        const int o = oh * 32 + nt * 8 + q * 2 + c;
                        float g = acc[mt][nt][h * 2 + c];
                        float y = rstd * (g - mu * smem[S_OFF + o]) + smem[BP_OFF + o];
                        float sv = y / (1.f + __expf(-y));
                        const int ch = o >> 4;
                        const int rr = rrb + ((o >> 2) & 3);
                        const int cl = clb + (o & 3);
                        outb[((ch * 32 + rr) << 5) + cl] = sv;
                    }
                }
            }
        }
        __syncthreads();
    }
}

extern "C" void kernel_launch(void* const* d_in, const int* in_sizes, int n_in,
                              void* d_out, int out_size)
{
    const float* x   = (const float*)d_in[0];
    const float* lnw = (const float*)d_in[1];
    const float* lnb = (const float*)d_in[2];
    const float* W   = (const float*)d_in[3];
    const float* b   = (const float*)d_in[4];
    float* out = (float*)d_out;

    cudaFuncSetAttribute(ln_gemm_silu,
                         cudaFuncAttributeMaxDynamicSharedMemorySize, SMEM_BYTES);

    int dev = 0, sms = 148;
    cudaGetDevice(&dev);
    cudaDeviceGetAttribute(&sms, cudaDevAttrMultiProcessorCount, dev);
    int grid = sms < NTILES ? sms : NTILES;

    ln_gemm_silu<<<grid, THREADS, SMEM_BYTES>>>(x, lnw, lnb, W, b, out);
}

// round 6
// speedup vs baseline: 2.2168x; 1.5760x over previous
#include <cuda_runtime.h>
#include <cstdint>
#include <math.h>

// LayerNorm(768) -> Linear(768->64) -> SiLU -> unpatchify, fused.
// LN folded into epilogue: y = rstd*(x@W'^T - mu*S) + b', W' = W*ln_w.
// tf32 mma.sync.m16n8k8. W' prepped into a __device__ global (L1/L2-resident),
// x streamed through double-buffered 64x32 swizzled smem slabs.
// 3 CTAs/SM for latency hiding; atomic work-stealing over 2048 tiles.

#define KDIM 768
#define ODIM 64
#define TILE_M 64
#define NTILES 2048
#define NSLABS 24

__device__ float d_Wbuf[ODIM * KDIM];   // [chunk(96)][o*8 + (k&3)*2 + ((k&7)>>2)]
__device__ float d_S[ODIM];
__device__ float d_bp[ODIM];
__device__ unsigned int d_ctr;

static __device__ __forceinline__ uint32_t f2tf(float f) {
    uint32_t r; asm("cvt.rna.tf32.f32 %0, %1;" : "=r"(r) : "f"(f)); return r;
}

static __device__ __forceinline__ void mma_tf32(float* d, const uint32_t* a, float2 bv) {
    asm volatile(
        "mma.sync.aligned.m16n8k8.row.col.f32.tf32.tf32.f32 "
        "{%0,%1,%2,%3}, {%4,%5,%6,%7}, {%8,%9}, {%0,%1,%2,%3};"
        : "+f"(d[0]), "+f"(d[1]), "+f"(d[2]), "+f"(d[3])
        : "r"(a[0]), "r"(a[1]), "r"(a[2]), "r"(a[3]),
          "r"(__float_as_uint(bv.x)), "r"(__float_as_uint(bv.y)));
}

// ---------------- prep kernels ----------------
__global__ void prep_w(const float* __restrict__ W, const float* __restrict__ lnw,
                       unsigned ctr_init) {
    int idx = blockIdx.x * 256 + threadIdx.x;
    if (idx == 0) d_ctr = ctr_init;
    if (idx < ODIM * KDIM) {
        int o = idx / KDIM, k = idx - o * KDIM;
        int kl = k & 7;
        d_Wbuf[(k >> 3) * 512 + o * 8 + (kl & 3) * 2 + (kl >> 2)] =
            __uint_as_float(f2tf(W[idx] * lnw[k]));
    }
}

__global__ void prep_sb(const float* __restrict__ W, const float* __restrict__ lnw,
                        const float* __restrict__ lnb, const float* __restrict__ b) {
    __shared__ float red[2][8];
    int o = blockIdx.x, t = threadIdx.x;
    float s = 0.f, bs = 0.f;
    for (int k = t; k < KDIM; k += 256) {
        float w = W[o * KDIM + k];
        s  += __uint_as_float(f2tf(w * lnw[k]));
        bs += lnb[k] * w;
    }
    #pragma unroll
    for (int d = 16; d; d >>= 1) {
        s  += __shfl_xor_sync(0xffffffffu, s, d);
        bs += __shfl_xor_sync(0xffffffffu, bs, d);
    }
    if ((t & 31) == 0) { red[0][t >> 5] = s; red[1][t >> 5] = bs; }
    __syncthreads();
    if (t == 0) {
        float S = 0.f, B = 0.f;
        #pragma unroll
        for (int i = 0; i < 8; i++) { S += red[0][i]; B += red[1][i]; }
        d_S[o] = S;
        d_bp[o] = b[o] + B;
    }
}

// ---------------- main kernel ----------------
__global__ void __launch_bounds__(256, 3)
ln_gemm_silu(const float* __restrict__ x, float* __restrict__ out)
{
    __shared__ float sxb[2][2048];          // two 64x32 slabs, XOR-swizzled
    __shared__ float smu[64], srs[64], sS[64], sbp[64];
    __shared__ unsigned s_next;

    const int tid  = threadIdx.x;
    const int lane = tid & 31;
    const int warp = tid >> 5;

    // consumer roles: warp = rg (rows rg*32..+31) x oh (n oh*16..+15)
    const int rg = warp >> 2;
    const int oh = warp & 3;
    const int u  = lane >> 2;     // 0..7
    const int q  = lane & 3;      // 0..3

    // producer mapping: thread owns row rowp, float4 cols c0 and c0+4
    const int rowp = tid >> 2;
    const int c0   = tid & 3;
    const int so0 = rowp * 32 + ((c0       ^ (rowp & 7)) << 2);
    const int so1 = rowp * 32 + (((c0 + 4) ^ (rowp & 7)) << 2);

    if (tid < 64) { sS[tid] = d_S[tid]; sbp[tid] = d_bp[tid]; }
    __syncthreads();

    unsigned tile = blockIdx.x;
    while (tile < NTILES) {
        float acc[2][2][4];
        #pragma unroll
        for (int mt = 0; mt < 2; mt++)
            #pragma unroll
            for (int nt = 0; nt < 2; nt++)
                #pragma unroll
                for (int c = 0; c < 4; c++) acc[mt][nt][c] = 0.f;

        float st_s = 0.f, st_ss = 0.f;
        const float4* xrow = (const float4*)x + (size_t)(tile * TILE_M + rowp) * 192;

        // prologue: slab 0
        float4 p0 = xrow[c0], p1 = xrow[c0 + 4];
        {
            st_s  += p0.x + p0.y + p0.z + p0.w + p1.x + p1.y + p1.z + p1.w;
            st_ss += p0.x*p0.x + p0.y*p0.y + p0.z*p0.z + p0.w*p0.w
                   + p1.x*p1.x + p1.y*p1.y + p1.z*p1.z + p1.w*p1.w;
            float4 t0, t1;
            t0.x = __uint_as_float(f2tf(p0.x)); t0.y = __uint_as_float(f2tf(p0.y));
            t0.z = __uint_as_float(f2tf(p0.z)); t0.w = __uint_as_float(f2tf(p0.w));
            t1.x = __uint_as_float(f2tf(p1.x)); t1.y = __uint_as_float(f2tf(p1.y));
            t1.z = __uint_as_float(f2tf(p1.z)); t1.w = __uint_as_float(f2tf(p1.w));
            *(float4*)&sxb[0][so0] = t0;
            *(float4*)&sxb[0][so1] = t1;
        }
        __syncthreads();

        for (int s = 0; s < NSLABS; s++) {
            const float* xb = sxb[s & 1];
            if (s + 1 < NSLABS) {
                p0 = xrow[(s + 1) * 8 + c0];
                p1 = xrow[(s + 1) * 8 + c0 + 4];
            }
            #pragma unroll
            for (int cl = 0; cl < 4; cl++) {
                const float* wb = d_Wbuf + (s * 4 + cl) * 512 + (oh * 16 + u) * 8 + q * 2;
                float2 b0 = __ldg((const float2*)wb);
                float2 b1 = __ldg((const float2*)(wb + 64));   // nt=1: +8 n rows
                #pragma unroll
                for (int mt = 0; mt < 2; mt++) {
                    const int r = rg * 32 + mt * 16 + u;
                    const int sw0 = ((cl * 2    ) ^ (r & 7)) << 2;
                    const int sw1 = ((cl * 2 + 1) ^ (r & 7)) << 2;
                    uint32_t af[4];
                    af[0] = __float_as_uint(xb[r * 32 + sw0 + q]);
                    af[1] = __float_as_uint(xb[(r + 8) * 32 + sw0 + q]);
                    af[2] = __float_as_uint(xb[r * 32 + sw1 + q]);
                    af[3] = __float_as_uint(xb[(r + 8) * 32 + sw1 + q]);
                    mma_tf32(acc[mt][0], af, b0);
                    mma_tf32(acc[mt][1], af, b1);
                }
            }
            if (s + 1 < NSLABS) {
                const int nb = (s + 1) & 1;
                st_s  += p0.x + p0.y + p0.z + p0.w + p1.x + p1.y + p1.z + p1.w;
                st_ss += p0.x*p0.x + p0.y*p0.y + p0.z*p0.z + p0.w*p0.w
                       + p1.x*p1.x + p1.y*p1.y + p1.z*p1.z + p1.w*p1.w;
                float4 t0, t1;
                t0.x = __uint_as_float(f2tf(p0.x)); t0.y = __uint_as_float(f2tf(p0.y));
                t0.z = __uint_as_float(f2tf(p0.z)); t0.w = __uint_as_float(f2tf(p0.w));
                t1.x = __uint_as_float(f2tf(p1.x)); t1.y = __uint_as_float(f2tf(p1.y));
                t1.z = __uint_as_float(f2tf(p1.z)); t1.w = __uint_as_float(f2tf(p1.w));
                *(float4*)&sxb[nb][so0] = t0;
                *(float4*)&sxb[nb][so1] = t1;
            }
            __syncthreads();
        }

        // row stats: 4 threads (tid^1, tid^2) share row rowp
        st_s  += __shfl_xor_sync(0xffffffffu, st_s,  1);
        st_ss += __shfl_xor_sync(0xffffffffu, st_ss, 1);
        st_s  += __shfl_xor_sync(0xffffffffu, st_s,  2);
        st_ss += __shfl_xor_sync(0xffffffffu, st_ss, 2);
        if ((tid & 3) == 0) {
            float mu = st_s * (1.f / 768.f);
            float rs = rsqrtf(st_ss * (1.f / 768.f) - mu * mu + 1e-5f);
            smu[rowp] = mu;
            srs[rowp] = rs;
        }
        __syncthreads();

        // epilogue: LN-correct, bias, SiLU, unpatchify (float2 stores)
        #pragma unroll
        for (int mt = 0; mt < 2; mt++) {
            #pragma unroll
            for (int h = 0; h < 2; h++) {
                const int rl = rg * 32 + mt * 16 + u + h * 8;
                const int grow = tile * TILE_M + rl;
                const float mu   = smu[rl];
                const float rstd = srs[rl];
                const int bidx = grow >> 6;
                const int c64  = grow & 63;
                const int rrb  = (c64 >> 3) << 2;
                const int clb  = (c64 & 7) << 2;
                float* outb = out + ((size_t)bidx << 12);
                #pragma unroll
                for (int nt = 0; nt < 2; nt++) {
                    const int o0 = oh * 16 + nt * 8 + q * 2;
                    float y0 = rstd * (acc[mt][nt][h * 2 + 0] - mu * sS[o0])     + sbp[o0];
                    float y1 = rstd * (acc[mt][nt][h * 2 + 1] - mu * sS[o0 + 1]) + sbp[o0 + 1];
                    float2 v;
                    v.x = y0 / (1.f + __expf(-y0));
                    v.y = y1 / (1.f + __expf(-y1));
                    const int ch = o0 >> 4;
                    const int rr = rrb + ((o0 >> 2) & 3);
                    const int cl = clb + (o0 & 3);
                    *(float2*)&outb[((ch * 32 + rr) << 5) + cl] = v;
                }
            }
        }

        if (tid == 0) s_next = atomicAdd(&d_ctr, 1u);
        __syncthreads();
        tile = s_next;
    }
}

extern "C" void kernel_launch(void* const* d_in, const int* in_sizes, int n_in,
                              void* d_out, int out_size)
{
    const float* x   = (const float*)d_in[0];
    const float* lnw = (const float*)d_in[1];
    const float* lnb = (const float*)d_in[2];
    const float* W   = (const float*)d_in[3];
    const float* b   = (const float*)d_in[4];
    float* out = (float*)d_out;

    int dev = 0, sms = 148;
    cudaGetDevice(&dev);
    cudaDeviceGetAttribute(&sms, cudaDevAttrMultiProcessorCount, dev);
    unsigned grid = (unsigned)(3 * sms);
    if (grid > NTILES) grid = NTILES;

    prep_w<<<(ODIM * KDIM + 255) / 256, 256>>>(W, lnw, grid);
    prep_sb<<<ODIM, 256>>>(W, lnw, lnb, b);
    ln_gemm_silu<<<grid, 256>>>(x, out);
}

// round 7
// speedup vs baseline: 3.2250x; 1.4548x over previous
#include <cuda_runtime.h>
#include <cuda_fp16.h>
#include <cstdint>
#include <math.h>

// LayerNorm(768) -> Linear(768->64) -> SiLU -> unpatchify, fused.
// LN folded into epilogue: y = rstd*(x@W'^T - mu*S) + b', W' = W*ln_w (fp16).
// fp16 mma.sync.m16n8k16, f32 accum. W' (96KB) in global, L1/L2-resident;
// x streamed with __ldcs through double-buffered fragment-layout smem slabs.

#define KDIM 768
#define ODIM 64
#define TILE_M 64
#define NTILES 2048            // 131072 / 64
#define NSLABS 24              // k-slabs of 32

__device__ __half d_Wh[48 * ODIM * 16];   // [c16][o][kl] fp16
__device__ float d_S[ODIM];
__device__ float d_bp[ODIM];
__device__ unsigned d_ctr;

static __device__ __forceinline__ uint32_t pack2(float lo, float hi) {
    uint32_t r;
    asm("cvt.rn.f16x2.f32 %0, %1, %2;" : "=r"(r) : "f"(hi), "f"(lo));
    return r;
}

static __device__ __forceinline__ void mma_f16(float* d,
    uint32_t a0, uint32_t a1, uint32_t a2, uint32_t a3,
    uint32_t b0, uint32_t b1)
{
    asm volatile(
        "mma.sync.aligned.m16n8k16.row.col.f32.f16.f16.f32 "
        "{%0,%1,%2,%3}, {%4,%5,%6,%7}, {%8,%9}, {%0,%1,%2,%3};"
        : "+f"(d[0]), "+f"(d[1]), "+f"(d[2]), "+f"(d[3])
        : "r"(a0), "r"(a1), "r"(a2), "r"(a3), "r"(b0), "r"(b1));
}

// ---------------- prep kernels ----------------
__global__ void prep_w(const float* __restrict__ W, const float* __restrict__ lnw,
                       unsigned ctr_init) {
    int idx = blockIdx.x * 256 + threadIdx.x;
    if (idx == 0) d_ctr = ctr_init;
    if (idx < ODIM * KDIM) {
        int o = idx / KDIM, k = idx - o * KDIM;
        d_Wh[((k >> 4) * ODIM + o) * 16 + (k & 15)] = __float2half_rn(W[idx] * lnw[k]);
    }
}

__global__ void prep_sb(const float* __restrict__ W, const float* __restrict__ lnw,
                        const float* __restrict__ lnb, const float* __restrict__ b) {
    __shared__ float red[2][8];
    int o = blockIdx.x, t = threadIdx.x;
    float s = 0.f, bs = 0.f;
    for (int k = t; k < KDIM; k += 256) {
        float w = W[o * KDIM + k];
        s  += __half2float(__float2half_rn(w * lnw[k]));
        bs += lnb[k] * w;
    }
    #pragma unroll
    for (int d = 16; d; d >>= 1) {
        s  += __shfl_xor_sync(0xffffffffu, s, d);
        bs += __shfl_xor_sync(0xffffffffu, bs, d);
    }
    if ((t & 31) == 0) { red[0][t >> 5] = s; red[1][t >> 5] = bs; }
    __syncthreads();
    if (t == 0) {
        float S = 0.f, B = 0.f;
        #pragma unroll
        for (int i = 0; i < 8; i++) { S += red[0][i]; B += red[1][i]; }
        d_S[o] = S;
        d_bp[o] = b[o] + B;
    }
}

// ---------------- main kernel ----------------
__global__ void __launch_bounds__(256, 3)
ln_gemm_silu(const float* __restrict__ x, float* __restrict__ out)
{
    // fragment-layout slabs: stage x 32 row-pairs x 8 slots x 16B = 4KB/stage
    __shared__ uint32_t sxb[2][2048];
    __shared__ float smu[64], srs[64], sS[64], sbp[64];
    __shared__ unsigned s_next;

    const int tid  = threadIdx.x;
    const int lane = tid & 31;
    const int warp = tid >> 5;

    // producer mapping: tid -> (row-pair, kc, q); one 16B slot per thread/slab
    const int prp = tid >> 3;                       // 0..31
    const int pkc = (tid >> 2) & 1;
    const int pq  = tid & 3;
    const int pr  = ((prp >> 3) << 4) + (prp & 7);  // row; partner pr+8
    const int psts = prp * 32 + ((((pkc ^ (prp & 1)) << 2) + pq) << 2);
    const int pk0  = pkc * 16 + pq * 2;             // k base within slab

    // consumer mapping: warp = rg (rows rg*16..+15) x oh (cols oh*32..+31)
    const int rg = warp >> 1;
    const int oh = warp & 1;
    const int u  = lane >> 2;
    const int q  = lane & 3;
    const int crp = rg * 8 + u;                     // row-pair index
    const int crow = rg * 16 + u;                   // row (partner +8)

    if (tid < ODIM) { sS[tid] = d_S[tid]; sbp[tid] = d_bp[tid]; }
    __syncthreads();

    unsigned tile = blockIdx.x;
    while (tile < NTILES) {
        float acc[4][4];
        #pragma unroll
        for (int nt = 0; nt < 4; nt++)
            #pragma unroll
            for (int c = 0; c < 4; c++) acc[nt][c] = 0.f;

        float st0 = 0.f, st1 = 0.f, st2 = 0.f, st3 = 0.f;   // s,ss for pr; pr+8

        const float* xr0 = x + (size_t)(tile * TILE_M + pr) * KDIM + pk0;
        const float* xr1 = xr0 + 8 * KDIM;

        // ---- prologue: slab 0 ----
        float2 v00 = __ldcs((const float2*)xr0);
        float2 v01 = __ldcs((const float2*)(xr0 + 8));
        float2 v10 = __ldcs((const float2*)xr1);
        float2 v11 = __ldcs((const float2*)(xr1 + 8));
        {
            st0 += v00.x + v00.y + v01.x + v01.y;
            st1 += v00.x*v00.x + v00.y*v00.y + v01.x*v01.x + v01.y*v01.y;
            st2 += v10.x + v10.y + v11.x + v11.y;
            st3 += v10.x*v10.x + v10.y*v10.y + v11.x*v11.x + v11.y*v11.y;
            uint4 t;
            t.x = pack2(v00.x, v00.y);   // (pr,   k 2q..)
            t.y = pack2(v01.x, v01.y);   // (pr,   k 2q+8..)
            t.z = pack2(v10.x, v10.y);   // (pr+8, k 2q..)
            t.w = pack2(v11.x, v11.y);   // (pr+8, k 2q+8..)
            *(uint4*)&sxb[0][psts] = t;
        }
        __syncthreads();

        for (int s = 0; s < NSLABS; s++) {
            if (s + 1 < NSLABS) {
                const float* p0 = xr0 + (s + 1) * 32;
                const float* p1 = xr1 + (s + 1) * 32;
                v00 = __ldcs((const float2*)p0);
                v01 = __ldcs((const float2*)(p0 + 8));
                v10 = __ldcs((const float2*)p1);
                v11 = __ldcs((const float2*)(p1 + 8));
            }

            // ---- compute slab s ----
            const uint32_t* xb = sxb[s & 1];
            #pragma unroll
            for (int kc = 0; kc < 2; kc++) {
                uint4 av = *(const uint4*)&xb[crp * 32 + ((((kc ^ (crp & 1)) << 2) + q) << 2)];
                const __half* wb = d_Wh + (size_t)((s * 2 + kc) * ODIM + oh * 32 + u) * 16;
                uint32_t b0[4], b1[4];
                #pragma unroll
                for (int nt = 0; nt < 4; nt++) {
                    b0[nt] = __ldg((const uint32_t*)(wb + nt * 128 + q * 2));
                    b1[nt] = __ldg((const uint32_t*)(wb + nt * 128 + q * 2 + 8));
                }
                #pragma unroll
                for (int nt = 0; nt < 4; nt++)
                    mma_f16(acc[nt], av.x, av.z, av.y, av.w, b0[nt], b1[nt]);
            }

            if (s + 1 < NSLABS) {
                st0 += v00.x + v00.y + v01.x + v01.y;
                st1 += v00.x*v00.x + v00.y*v00.y + v01.x*v01.x + v01.y*v01.y;
                st2 += v10.x + v10.y + v11.x + v11.y;
                st3 += v10.x*v10.x + v10.y*v10.y + v11.x*v11.x + v11.y*v11.y;
                uint4 t;
                t.x = pack2(v00.x, v00.y);
                t.y = pack2(v01.x, v01.y);
                t.z = pack2(v10.x, v10.y);
                t.w = pack2(v11.x, v11.y);
                *(uint4*)&sxb[(s + 1) & 1][psts] = t;
            }
            __syncthreads();
        }

        // ---- row stats: 8 threads (kc,q) share rows pr, pr+8 ----
        #pragma unroll
        for (int d = 1; d < 8; d <<= 1) {
            st0 += __shfl_xor_sync(0xffffffffu, st0, d);
            st1 += __shfl_xor_sync(0xffffffffu, st1, d);
            st2 += __shfl_xor_sync(0xffffffffu, st2, d);
            st3 += __shfl_xor_sync(0xffffffffu, st3, d);
        }
        if ((tid & 7) == 0) {
            float mu0 = st0 * (1.f / 768.f);
            float mu1 = st2 * (1.f / 768.f);
            smu[pr]     = mu0;
            smu[pr + 8] = mu1;
            srs[pr]     = rsqrtf(st1 * (1.f / 768.f) - mu0 * mu0 + 1e-5f);
            srs[pr + 8] = rsqrtf(st3 * (1.f / 768.f) - mu1 * mu1 + 1e-5f);
        }
        __syncthreads();

        // ---- epilogue: LN-correct, bias, SiLU, unpatchify ----
        #pragma unroll
        for (int h = 0; h < 2; h++) {
            const int rl = crow + h * 8;
            const int grow = tile * TILE_M + rl;
            const float mu   = smu[rl];
            const float rstd = srs[rl];
            const int bidx = grow >> 6;
            const int c64  = grow & 63;
            const int rrb  = (c64 >> 3) << 2;
            const int clb  = (c64 & 7) << 2;
            float* outb = out + ((size_t)bidx << 12);
            #pragma unroll
            for (int nt = 0; nt < 4; nt++) {
                const int o0 = oh * 32 + nt * 8 + q * 2;
                float y0 = rstd * (acc[nt][h * 2 + 0] - mu * sS[o0])     + sbp[o0];
                float y1 = rstd * (acc[nt][h * 2 + 1] - mu * sS[o0 + 1]) + sbp[o0 + 1];
                float2 v;
                v.x = y0 / (1.f + __expf(-y0));
                v.y = y1 / (1.f + __expf(-y1));
                const int ch = o0 >> 4;
                const int rr = rrb + ((o0 >> 2) & 3);
                const int cl = clb + (o0 & 3);
                *(float2*)&outb[((ch * 32 + rr) << 5) + cl] = v;
            }
        }

        if (tid == 0) s_next = atomicAdd(&d_ctr, 1u);
        __syncthreads();
        tile = s_next;
    }
}

extern "C" void kernel_launch(void* const* d_in, const int* in_sizes, int n_in,
                              void* d_out, int out_size)
{
    const float* x   = (const float*)d_in[0];
    const float* lnw = (const float*)d_in[1];
    const float* lnb = (const float*)d_in[2];
    const float* W   = (const float*)d_in[3];
    const float* b   = (const float*)d_in[4];
    float* out = (float*)d_out;

    int dev = 0, sms = 148;
    cudaGetDevice(&dev);
    cudaDeviceGetAttribute(&sms, cudaDevAttrMultiProcessorCount, dev);
    unsigned grid = (unsigned)(3 * sms);
    if (grid > NTILES) grid = NTILES;

    prep_w<<<(ODIM * KDIM + 255) / 256, 256>>>(W, lnw, grid);
    prep_sb<<<ODIM, 256>>>(W, lnw, lnb, b);
    ln_gemm_silu<<<grid, 256>>>(x, out);
}

// round 8
// speedup vs baseline: 3.6017x; 1.1168x over previous
#include <cuda_runtime.h>
#include <cuda_fp16.h>
#include <cstdint>
#include <math.h>

// LayerNorm(768) -> Linear(768->64) -> SiLU -> unpatchify, fused.
// LN folded into epilogue: y = rstd*(x@W'^T - mu*S) + b', W' = W*ln_w (fp16).
// fp16 mma.sync.m16n8k16. Warp-autonomous: A-fragments gathered directly from
// global x (no smem staging, no mainloop syncthreads), W' fragment-interleaved
// in global (L1-resident), depth-2 register ping-pong prefetch.

#define KDIM 768
#define ODIM 64
#define TILE_M 64
#define NTILES 2048            // 131072 / 64
#define NSLABS 24              // k-slabs of 32

__device__ __half d_Wh[48 * ODIM * 16];   // [c16][o][frag-interleaved kl]
__device__ float d_S[ODIM];
__device__ float d_bp[ODIM];
__device__ unsigned d_ctr;

static __device__ __forceinline__ uint32_t pack2(float lo, float hi) {
    uint32_t r;
    asm("cvt.rn.f16x2.f32 %0, %1, %2;" : "=r"(r) : "f"(hi), "f"(lo));
    return r;
}

static __device__ __forceinline__ void mma_f16(float* d,
    uint32_t a0, uint32_t a1, uint32_t a2, uint32_t a3,
    uint32_t b0, uint32_t b1)
{
    asm volatile(
        "mma.sync.aligned.m16n8k16.row.col.f32.f16.f16.f32 "
        "{%0,%1,%2,%3}, {%4,%5,%6,%7}, {%8,%9}, {%0,%1,%2,%3};"
        : "+f"(d[0]), "+f"(d[1]), "+f"(d[2]), "+f"(d[3])
        : "r"(a0), "r"(a1), "r"(a2), "r"(a3), "r"(b0), "r"(b1));
}

// ---------------- prep kernels ----------------
// frag-interleaved position of k within a 16-half group:
// pos = ((k&7)>>1)*4 + ((k>>3)&1)*2 + (k&1)  ->  lane q reads one u64 at q*4.
__global__ void prep_w(const float* __restrict__ W, const float* __restrict__ lnw,
                       unsigned ctr_init) {
    int idx = blockIdx.x * 256 + threadIdx.x;
    if (idx == 0) d_ctr = ctr_init;
    if (idx < ODIM * KDIM) {
        int o = idx / KDIM, k = idx - o * KDIM;
        int kl = k & 15;
        int pos = ((kl & 7) >> 1) * 4 + ((kl >> 3) & 1) * 2 + (kl & 1);
        d_Wh[((k >> 4) * ODIM + o) * 16 + pos] = __float2half_rn(W[idx] * lnw[k]);
    }
}

__global__ void prep_sb(const float* __restrict__ W, const float* __restrict__ lnw,
                        const float* __restrict__ lnb, const float* __restrict__ b) {
    __shared__ float red[2][8];
    int o = blockIdx.x, t = threadIdx.x;
    float s = 0.f, bs = 0.f;
    for (int k = t; k < KDIM; k += 256) {
        float w = W[o * KDIM + k];
        s  += __half2float(__float2half_rn(w * lnw[k]));
        bs += lnb[k] * w;
    }
    #pragma unroll
    for (int d = 16; d; d >>= 1) {
        s  += __shfl_xor_sync(0xffffffffu, s, d);
        bs += __shfl_xor_sync(0xffffffffu, bs, d);
    }
    if ((t & 31) == 0) { red[0][t >> 5] = s; red[1][t >> 5] = bs; }
    __syncthreads();
    if (t == 0) {
        float S = 0.f, B = 0.f;
        #pragma unroll
        for (int i = 0; i < 8; i++) { S += red[0][i]; B += red[1][i]; }
        d_S[o] = S;
        d_bp[o] = b[o] + B;
    }
}

// ---------------- main kernel ----------------
__global__ void __launch_bounds__(256, 2)
ln_gemm_silu(const float* __restrict__ x, float* __restrict__ out)
{
    __shared__ float sS[64], sbp[64];
    __shared__ unsigned s_next;

    const int tid  = threadIdx.x;
    const int lane = tid & 31;
    const int warp = tid >> 5;

    // warp = rg (rows rg*16 + {u, u+8}) x oh (cols oh*32..+31)
    const int rg = warp >> 1;
    const int oh = warp & 1;
    const int u  = lane >> 2;
    const int q  = lane & 3;

    if (tid < ODIM) { sS[tid] = d_S[tid]; sbp[tid] = d_bp[tid]; }
    __syncthreads();

    const uint2* __restrict__ Wv = (const uint2*)d_Wh;

    unsigned tile = blockIdx.x;
    while (tile < NTILES) {
        float acc[4][4];
        #pragma unroll
        for (int nt = 0; nt < 4; nt++)
            #pragma unroll
            for (int c = 0; c < 4; c++) acc[nt][c] = 0.f;

        float st0 = 0.f, st1 = 0.f, st2 = 0.f, st3 = 0.f;

        const float* xu  = x + (size_t)(tile * TILE_M + rg * 16 + u) * KDIM + q * 2;
        const float* xu8 = xu + 8 * KDIM;

        // ping-pong fragment-load buffers: [kc*4 + {u:k0, u:k0+8, u8:k0, u8:k0+8}]
        float2 lv[2][8];
        #pragma unroll
        for (int kc = 0; kc < 2; kc++) {
            lv[0][kc * 4 + 0] = __ldcs((const float2*)(xu  + kc * 16));
            lv[0][kc * 4 + 1] = __ldcs((const float2*)(xu  + kc * 16 + 8));
            lv[0][kc * 4 + 2] = __ldcs((const float2*)(xu8 + kc * 16));
            lv[0][kc * 4 + 3] = __ldcs((const float2*)(xu8 + kc * 16 + 8));
        }

        int buf = 0;
        #pragma unroll 4
        for (int s = 0; s < NSLABS; s++) {
            const float2* L = lv[buf];

            // stats on this slab's values
            #pragma unroll
            for (int kc = 0; kc < 2; kc++) {
                float2 a0 = L[kc * 4 + 0], a1 = L[kc * 4 + 1];
                float2 b0 = L[kc * 4 + 2], b1 = L[kc * 4 + 3];
                st0 += a0.x + a0.y + a1.x + a1.y;
                st1 += a0.x*a0.x + a0.y*a0.y + a1.x*a1.x + a1.y*a1.y;
                st2 += b0.x + b0.y + b1.x + b1.y;
                st3 += b0.x*b0.x + b0.y*b0.y + b1.x*b1.x + b1.y*b1.y;
            }

            // pack A fragments
            uint32_t af[2][4];
            #pragma unroll
            for (int kc = 0; kc < 2; kc++) {
                af[kc][0] = pack2(L[kc * 4 + 0].x, L[kc * 4 + 0].y);  // (u,   2q)
                af[kc][1] = pack2(L[kc * 4 + 2].x, L[kc * 4 + 2].y);  // (u+8, 2q)
                af[kc][2] = pack2(L[kc * 4 + 1].x, L[kc * 4 + 1].y);  // (u,   2q+8)
                af[kc][3] = pack2(L[kc * 4 + 3].x, L[kc * 4 + 3].y);  // (u+8, 2q+8)
            }

            // prefetch next slab into the other buffer
            if (s + 1 < NSLABS) {
                float2* N = lv[buf ^ 1];
                const int o32 = (s + 1) * 32;
                #pragma unroll
                for (int kc = 0; kc < 2; kc++) {
                    N[kc * 4 + 0] = __ldcs((const float2*)(xu  + o32 + kc * 16));
                    N[kc * 4 + 1] = __ldcs((const float2*)(xu  + o32 + kc * 16 + 8));
                    N[kc * 4 + 2] = __ldcs((const float2*)(xu8 + o32 + kc * 16));
                    N[kc * 4 + 3] = __ldcs((const float2*)(xu8 + o32 + kc * 16 + 8));
                }
            }

            // W fragments (one LDG.64 per nt per kc) + MMA
            #pragma unroll
            for (int kc = 0; kc < 2; kc++) {
                const int c16 = s * 2 + kc;
                const uint2* wb = Wv + (size_t)(c16 * ODIM + oh * 32 + u) * 4 + q;
                #pragma unroll
                for (int nt = 0; nt < 4; nt++) {
                    uint2 bv = __ldg(wb + nt * 32);   // +8 o rows = 8*16 halves = 32 uint2
                    mma_f16(acc[nt], af[kc][0], af[kc][1], af[kc][2], af[kc][3],
                            bv.x, bv.y);
                }
            }
            buf ^= 1;
        }

        // ---- row stats: reduce over the 4 q-lanes sharing each row ----
        st0 += __shfl_xor_sync(0xffffffffu, st0, 1);
        st1 += __shfl_xor_sync(0xffffffffu, st1, 1);
        st2 += __shfl_xor_sync(0xffffffffu, st2, 1);
        st3 += __shfl_xor_sync(0xffffffffu, st3, 1);
        st0 += __shfl_xor_sync(0xffffffffu, st0, 2);
        st1 += __shfl_xor_sync(0xffffffffu, st1, 2);
        st2 += __shfl_xor_sync(0xffffffffu, st2, 2);
        st3 += __shfl_xor_sync(0xffffffffu, st3, 2);

        float mu[2], rs[2];
        mu[0] = st0 * (1.f / 768.f);
        mu[1] = st2 * (1.f / 768.f);
        rs[0] = rsqrtf(st1 * (1.f / 768.f) - mu[0] * mu[0] + 1e-5f);
        rs[1] = rsqrtf(st3 * (1.f / 768.f) - mu[1] * mu[1] + 1e-5f);

        // ---- epilogue: LN-correct, bias, SiLU, unpatchify ----
        #pragma unroll
        for (int h = 0; h < 2; h++) {
            const int grow = tile * TILE_M + rg * 16 + u + h * 8;
            const int bidx = grow >> 6;
            const int c64  = grow & 63;
            const int rrb  = (c64 >> 3) << 2;
            const int clb  = (c64 & 7) << 2;
            float* outb = out + ((size_t)bidx << 12);
            #pragma unroll
            for (int nt = 0; nt < 4; nt++) {
                const int o0 = oh * 32 + nt * 8 + q * 2;
                float y0 = rs[h] * (acc[nt][h * 2 + 0] - mu[h] * sS[o0])     + sbp[o0];
                float y1 = rs[h] * (acc[nt][h * 2 + 1] - mu[h] * sS[o0 + 1]) + sbp[o0 + 1];
                float2 v;
                v.x = y0 / (1.f + __expf(-y0));
                v.y = y1 / (1.f + __expf(-y1));
                const int ch = o0 >> 4;
                const int rr = rrb + ((o0 >> 2) & 3);
                const int cl = clb + (o0 & 3);
                *(float2*)&outb[((ch * 32 + rr) << 5) + cl] = v;
            }
        }

        __syncthreads();
        if (tid == 0) s_next = atomicAdd(&d_ctr, 1u);
        __syncthreads();
        tile = s_next;
    }
}

extern "C" void kernel_launch(void* const* d_in, const int* in_sizes, int n_in,
                              void* d_out, int out_size)
{
    const float* x   = (const float*)d_in[0];
    const float* lnw = (const float*)d_in[1];
    const float* lnb = (const float*)d_in[2];
    const float* W   = (const float*)d_in[3];
    const float* b   = (const float*)d_in[4];
    float* out = (float*)d_out;

    int dev = 0, sms = 148;
    cudaGetDevice(&dev);
    cudaDeviceGetAttribute(&sms, cudaDevAttrMultiProcessorCount, dev);
    unsigned grid = (unsigned)(2 * sms);
    if (grid > NTILES) grid = NTILES;

    prep_w<<<(ODIM * KDIM + 255) / 256, 256>>>(W, lnw, grid);
    prep_sb<<<ODIM, 256>>>(W, lnw, lnb, b);
    ln_gemm_silu<<<grid, 256>>>(x, out);
}